// round 9
// baseline (speedup 1.0000x reference)
#include <cuda_runtime.h>
#include <math.h>

#define SEQV  5
#define ALPHA 0.2f

// Precomputed transposed column-softmax of w_raw, padded rows of 66:
// g_Wt[d*66 + c] = softmax(w_raw*500, axis=0)[c][d]
__device__ float g_Wt[64 * 66];

// ---- 16-lane (half-warp) reductions ----
__device__ __forceinline__ float hmax16(float v) {
    v = fmaxf(v, __shfl_xor_sync(0xffffffffu, v, 1));
    v = fmaxf(v, __shfl_xor_sync(0xffffffffu, v, 2));
    v = fmaxf(v, __shfl_xor_sync(0xffffffffu, v, 4));
    v = fmaxf(v, __shfl_xor_sync(0xffffffffu, v, 8));
    return v;
}
__device__ __forceinline__ float hsum16(float v) {
    v += __shfl_xor_sync(0xffffffffu, v, 1);
    v += __shfl_xor_sync(0xffffffffu, v, 2);
    v += __shfl_xor_sync(0xffffffffu, v, 4);
    v += __shfl_xor_sync(0xffffffffu, v, 8);
    return v;
}

// ---------------------------------------------------------------------------
// Prep kernel: block d computes softmax column d of w_raw*500 (runs once).
// ---------------------------------------------------------------------------
__global__ void prep_w_kernel(const float* __restrict__ w_raw) {
    const int d = blockIdx.x;      // column
    const int c = threadIdx.x;     // row
    __shared__ float red[4];

    float val = w_raw[c * 64 + d] * 500.0f;          // 100 * GAMMA2
    float m = val;
#pragma unroll
    for (int off = 16; off; off >>= 1)
        m = fmaxf(m, __shfl_xor_sync(0xffffffffu, m, off));
    if ((c & 31) == 0) red[c >> 5] = m;
    __syncthreads();
    m = fmaxf(red[0], red[1]);

    float e = __expf(val - m);
    float Z = e;
#pragma unroll
    for (int off = 16; off; off >>= 1)
        Z += __shfl_xor_sync(0xffffffffu, Z, off);
    if ((c & 31) == 0) red[2 + (c >> 5)] = Z;
    __syncthreads();
    Z = red[2] + red[3];

    g_Wt[d * 66 + c] = __fdividef(e, Z);
}

// ---------------------------------------------------------------------------
// Main kernel: 256 threads = 8 warps = 16 batch elements (one per half-warp).
// Lane k (0..15) owns elements 4k..4k+3 of every 64-float row -> one float4
// per lane, 256B coalesced per half-warp. W is copied (not computed) from the
// precomputed global. The 64x64 mat-vec stays 4-b-batched on warps 0..3
// (lane owns c={2*lane, 2*lane+1}); warps 4..7 issue their gathers meanwhile.
// ---------------------------------------------------------------------------
__global__ __launch_bounds__(256, 5) void rumc_kernel(
    const int*   __restrict__ u,
    const int*   __restrict__ X,
    const int*   __restrict__ y,
    const float* __restrict__ item_emb,
    const float* __restrict__ user_emb,
    const float* __restrict__ ae_raw,
    float*       __restrict__ out,
    int B)
{
    __shared__ float sW[64 * 66];      // 16.9KB
    __shared__ float sAey[16 * 68];    // ae[y] per b (4.25KB)
    __shared__ float sV[16 * 68];      // v per b (4.25KB)

    const int tid  = threadIdx.x;
    const int warp = tid >> 5;
    const int lane = tid & 31;
    const int k    = lane & 15;            // lane within half-warp
    const int bloc = warp * 2 + (lane >> 4);

    int b = blockIdx.x * 16 + bloc;
    const bool valid = (b < B);
    if (!valid) b = B - 1;

    // ---- issue index loads + ae[y] gather FIRST (overlap with W copy) ----
    const int yi = y[b];
    const int ui = u[b];
    int xs[SEQV];
#pragma unroll
    for (int s = 0; s < SEQV; s++) xs[s] = X[b * SEQV + s];

    float4 A = *(const float4*)(ae_raw + (size_t)yi * 64 + 4 * k);

    // ================= copy precomputed W into smem ==========================
    {
        const float2* src = (const float2*)g_Wt;
        float2*       dst = (float2*)sW;
#pragma unroll
        for (int i = 0; i < 8; i++)
            dst[tid + 256 * i] = src[tid + 256 * i];
        if (tid < 2112 - 2048)
            dst[tid + 2048] = src[tid + 2048];
    }

    // ================= ae[y] softmax -> smem =================================
    {
        float a0 = A.x * 50.0f, a1 = A.y * 50.0f;     // 10*GAMMA1
        float a2 = A.z * 50.0f, a3 = A.w * 50.0f;
        float m = hmax16(fmaxf(fmaxf(a0, a1), fmaxf(a2, a3)));
        a0 = __expf(a0 - m); a1 = __expf(a1 - m);
        a2 = __expf(a2 - m); a3 = __expf(a3 - m);
        float Z = hsum16((a0 + a1) + (a2 + a3));
        float inv = __fdividef(1.0f, Z);
        *(float4*)(sAey + bloc * 68 + 4 * k) =
            make_float4(a0 * inv, a1 * inv, a2 * inv, a3 * inv);
    }

    // ---- prefetch y-item row, step-0 ae row, step-0 item row ----
    float4 Y = make_float4(0.f, 0.f, 0.f, 0.f);
    if (yi != 0)
        Y = *(const float4*)(item_emb + (size_t)yi * 64 + 4 * k);
    float4 Fc = *(const float4*)(ae_raw + (size_t)xs[0] * 64 + 4 * k);
    float4 Xc = make_float4(0.f, 0.f, 0.f, 0.f);
    if (xs[0] != 0)
        Xc = *(const float4*)(item_emb + (size_t)xs[0] * 64 + 4 * k);

    __syncthreads();   // W copy + all 16 aey rows visible

    // ================= batched mat-vec: warps 0..3, 4 b each =================
    if (warp < 4) {
        float acc0x = 0.f, acc0y = 0.f, acc1x = 0.f, acc1y = 0.f;
        float acc2x = 0.f, acc2y = 0.f, acc3x = 0.f, acc3y = 0.f;
        const int bB = warp * 4;
        const float* aey0 = sAey + (bB + 0) * 68;
        const float* aey1 = sAey + (bB + 1) * 68;
        const float* aey2 = sAey + (bB + 2) * 68;
        const float* aey3 = sAey + (bB + 3) * 68;
#pragma unroll
        for (int d4 = 0; d4 < 16; d4++) {
            float2 w0 = *(const float2*)(sW + (4 * d4 + 0) * 66 + 2 * lane);
            float2 w1 = *(const float2*)(sW + (4 * d4 + 1) * 66 + 2 * lane);
            float2 w2 = *(const float2*)(sW + (4 * d4 + 2) * 66 + 2 * lane);
            float2 w3 = *(const float2*)(sW + (4 * d4 + 3) * 66 + 2 * lane);

            float4 a;
            a = *(const float4*)(aey0 + 4 * d4);
            acc0x = fmaf(w0.x, a.x, fmaf(w1.x, a.y, fmaf(w2.x, a.z, fmaf(w3.x, a.w, acc0x))));
            acc0y = fmaf(w0.y, a.x, fmaf(w1.y, a.y, fmaf(w2.y, a.z, fmaf(w3.y, a.w, acc0y))));
            a = *(const float4*)(aey1 + 4 * d4);
            acc1x = fmaf(w0.x, a.x, fmaf(w1.x, a.y, fmaf(w2.x, a.z, fmaf(w3.x, a.w, acc1x))));
            acc1y = fmaf(w0.y, a.x, fmaf(w1.y, a.y, fmaf(w2.y, a.z, fmaf(w3.y, a.w, acc1y))));
            a = *(const float4*)(aey2 + 4 * d4);
            acc2x = fmaf(w0.x, a.x, fmaf(w1.x, a.y, fmaf(w2.x, a.z, fmaf(w3.x, a.w, acc2x))));
            acc2y = fmaf(w0.y, a.x, fmaf(w1.y, a.y, fmaf(w2.y, a.z, fmaf(w3.y, a.w, acc2y))));
            a = *(const float4*)(aey3 + 4 * d4);
            acc3x = fmaf(w0.x, a.x, fmaf(w1.x, a.y, fmaf(w2.x, a.z, fmaf(w3.x, a.w, acc3x))));
            acc3y = fmaf(w0.y, a.x, fmaf(w1.y, a.y, fmaf(w2.y, a.z, fmaf(w3.y, a.w, acc3y))));
        }
        *(float2*)(sV + (bB + 0) * 68 + 2 * lane) = make_float2(acc0x, acc0y);
        *(float2*)(sV + (bB + 1) * 68 + 2 * lane) = make_float2(acc1x, acc1y);
        *(float2*)(sV + (bB + 2) * 68 + 2 * lane) = make_float2(acc2x, acc2y);
        *(float2*)(sV + (bB + 3) * 68 + 2 * lane) = make_float2(acc3x, acc3y);
    }
    __syncthreads();   // v visible to all

    // ================= epilogue: half-warp per b =============================
    float4 V = *(const float4*)(sV + bloc * 68 + 4 * k);

    // user row: issue now, consumed only after the loop
    float4 U = *(const float4*)(user_emb + (size_t)ui * 64 + 4 * k);

    float mrun = -1e30f, Zrun = 0.0f;
    float4 P = make_float4(0.f, 0.f, 0.f, 0.f);

#pragma unroll
    for (int s = 0; s < SEQV; s++) {
        // this step's rows (prefetched)
        float4 F  = Fc;
        float4 Xe = Xc;
        // prefetch next step's ae + item rows
        if (s + 1 < SEQV) {
            const int xn = xs[s + 1];
            Fc = *(const float4*)(ae_raw + (size_t)xn * 64 + 4 * k);
            if (xn != 0)
                Xc = *(const float4*)(item_emb + (size_t)xn * 64 + 4 * k);
            else
                Xc = make_float4(0.f, 0.f, 0.f, 0.f);
        }

        float f0 = F.x * 50.0f, f1 = F.y * 50.0f;
        float f2 = F.z * 50.0f, f3 = F.w * 50.0f;
        float mm = hmax16(fmaxf(fmaxf(f0, f1), fmaxf(f2, f3)));
        f0 = __expf(f0 - mm); f1 = __expf(f1 - mm);
        f2 = __expf(f2 - mm); f3 = __expf(f3 - mm);
        float num = fmaf(f0, V.x, fmaf(f1, V.y, fmaf(f2, V.z, f3 * V.w)));
        float den = (f0 + f1) + (f2 + f3);
        float dot = fmaf(Xe.x, Y.x, fmaf(Xe.y, Y.y, fmaf(Xe.z, Y.z, Xe.w * Y.w)));
        num = hsum16(num);
        den = hsum16(den);
        dot = hsum16(dot);
        float fac = __fdividef(num, den);

        const float tf = 0.6f + 0.1f * (float)s;     // time factor, BETA=1
        float sc = dot * __expf(fac) * tf;

        // online softmax accumulation
        float mnew = fmaxf(mrun, sc);
        float r = __expf(mrun - mnew);
        float e = __expf(sc - mnew);
        Zrun = fmaf(Zrun, r, e);
        P.x = fmaf(P.x, r, e * Xe.x); P.y = fmaf(P.y, r, e * Xe.y);
        P.z = fmaf(P.z, r, e * Xe.z); P.w = fmaf(P.w, r, e * Xe.w);
        mrun = mnew;
    }

    const float scale = __fdividef(ALPHA, Zrun);
    float d;
    d =          fmaf(P.x, scale, U.x) * Y.x;
    d = fmaf(fmaf(P.y, scale, U.y), Y.y, d);
    d = fmaf(fmaf(P.z, scale, U.z), Y.z, d);
    d = fmaf(fmaf(P.w, scale, U.w), Y.w, d);
    d = hsum16(d);

    if (valid && k == 0)
        out[b] = __fdividef(1.0f, 1.0f + __expf(-d));
}

// ---------------------------------------------------------------------------
// Launcher — inputs (metadata order): u[int B], X[int B*5], y[int B],
//   item_emb[f32 (I+1)*64], user_emb[f32 U*64], ae_raw[f32 (I+1)*64],
//   w_raw[f32 64*64].  Output: f32 [B].
// ---------------------------------------------------------------------------
extern "C" void kernel_launch(void* const* d_in, const int* in_sizes, int n_in,
                              void* d_out, int out_size) {
    const int*   u        = (const int*)  d_in[0];
    const int*   X        = (const int*)  d_in[1];
    const int*   y        = (const int*)  d_in[2];
    const float* item_emb = (const float*)d_in[3];
    const float* user_emb = (const float*)d_in[4];
    const float* ae_raw   = (const float*)d_in[5];
    const float* w_raw    = (const float*)d_in[6];
    float* out = (float*)d_out;

    const int B = in_sizes[0];

    prep_w_kernel<<<64, 64>>>(w_raw);

    const int blocks = (B + 15) / 16;   // 16 batch elems per 256-thread block
    rumc_kernel<<<blocks, 256>>>(u, X, y, item_emb, user_emb, ae_raw, out, B);
}

// round 10
// speedup vs baseline: 1.1193x; 1.1193x over previous
#include <cuda_runtime.h>
#include <math.h>

#define SEQV  5
#define ALPHA 0.2f

// Precomputed transposed column-softmax of w_raw, padded rows of 66:
// g_Wt[d*66 + c] = softmax(w_raw*500, axis=0)[c][d]
__device__ float g_Wt[64 * 66];

// ---- 8-lane (octet) reductions: xor 1,2,4 stay inside the octet ----
__device__ __forceinline__ float omax8(float v) {
    v = fmaxf(v, __shfl_xor_sync(0xffffffffu, v, 1));
    v = fmaxf(v, __shfl_xor_sync(0xffffffffu, v, 2));
    v = fmaxf(v, __shfl_xor_sync(0xffffffffu, v, 4));
    return v;
}
__device__ __forceinline__ float osum8(float v) {
    v += __shfl_xor_sync(0xffffffffu, v, 1);
    v += __shfl_xor_sync(0xffffffffu, v, 2);
    v += __shfl_xor_sync(0xffffffffu, v, 4);
    return v;
}

// ---------------------------------------------------------------------------
// Prep kernel: block d computes softmax column d of w_raw*500 (runs once).
// ---------------------------------------------------------------------------
__global__ void prep_w_kernel(const float* __restrict__ w_raw) {
    const int d = blockIdx.x;      // column
    const int c = threadIdx.x;     // row
    __shared__ float red[4];

    float val = w_raw[c * 64 + d] * 500.0f;          // 100 * GAMMA2
    float m = val;
#pragma unroll
    for (int off = 16; off; off >>= 1)
        m = fmaxf(m, __shfl_xor_sync(0xffffffffu, m, off));
    if ((c & 31) == 0) red[c >> 5] = m;
    __syncthreads();
    m = fmaxf(red[0], red[1]);

    float e = __expf(val - m);
    float Z = e;
#pragma unroll
    for (int off = 16; off; off >>= 1)
        Z += __shfl_xor_sync(0xffffffffu, Z, off);
    if ((c & 31) == 0) red[2 + (c >> 5)] = Z;
    __syncthreads();
    Z = red[2] + red[3];

    g_Wt[d * 66 + c] = __fdividef(e, Z);
}

// ---------------------------------------------------------------------------
// Main kernel: 256 threads = 8 warps = 32 batch elements (4 per warp, one per
// 8-lane octet). W copied from the precomputed global. ae rows prefetched 2
// steps ahead, item rows 1 step ahead; user row loaded inside the last step.
// ---------------------------------------------------------------------------
__global__ __launch_bounds__(256, 4) void rumc_kernel(
    const int*   __restrict__ u,
    const int*   __restrict__ X,
    const int*   __restrict__ y,
    const float* __restrict__ item_emb,
    const float* __restrict__ user_emb,
    const float* __restrict__ ae_raw,
    float*       __restrict__ out,
    int B)
{
    __shared__ float sW[64 * 66];      // 16.9KB
    __shared__ float sAV[32 * 68];     // ae[y] per b, overwritten in-place by v

    const int tid  = threadIdx.x;
    const int warp = tid >> 5;
    const int lane = tid & 31;
    const int o    = lane >> 3;
    const int k8   = lane & 7;

    const int bloc = warp * 4 + o;
    int b = blockIdx.x * 32 + bloc;
    const bool valid = (b < B);
    if (!valid) b = B - 1;

    // ---- issue index loads + ae[y] gather FIRST (overlap with W copy) ----
    const int yi = y[b];
    const int ui = u[b];
    int xs[SEQV];
#pragma unroll
    for (int s = 0; s < SEQV; s++) xs[s] = X[b * SEQV + s];

    const float* ayp = ae_raw + (size_t)yi * 64;
    float4 A0 = *(const float4*)(ayp + 4 * k8);
    float4 A1 = *(const float4*)(ayp + 32 + 4 * k8);

    // ================= copy precomputed W into smem ==========================
    {
        const float2* src = (const float2*)g_Wt;
        float2*       dst = (float2*)sW;
#pragma unroll
        for (int i = 0; i < 8; i++)
            dst[tid + 256 * i] = src[tid + 256 * i];
        if (tid < 2112 - 2048)
            dst[tid + 2048] = src[tid + 2048];
    }

    // ================= ae[y] softmax -> smem =================================
    {
        float a0 = A0.x * 50.0f, a1 = A0.y * 50.0f, a2 = A0.z * 50.0f, a3 = A0.w * 50.0f;
        float a4 = A1.x * 50.0f, a5 = A1.y * 50.0f, a6 = A1.z * 50.0f, a7 = A1.w * 50.0f;
        float m = fmaxf(fmaxf(fmaxf(a0, a1), fmaxf(a2, a3)),
                        fmaxf(fmaxf(a4, a5), fmaxf(a6, a7)));
        m = omax8(m);
        a0 = __expf(a0 - m); a1 = __expf(a1 - m); a2 = __expf(a2 - m); a3 = __expf(a3 - m);
        a4 = __expf(a4 - m); a5 = __expf(a5 - m); a6 = __expf(a6 - m); a7 = __expf(a7 - m);
        float Z = osum8(((a0 + a1) + (a2 + a3)) + ((a4 + a5) + (a6 + a7)));
        float inv = __fdividef(1.0f, Z);
        *(float4*)(sAV + bloc * 68 + 4 * k8) =
            make_float4(a0 * inv, a1 * inv, a2 * inv, a3 * inv);
        *(float4*)(sAV + bloc * 68 + 32 + 4 * k8) =
            make_float4(a4 * inv, a5 * inv, a6 * inv, a7 * inv);
    }

    // ---- prefetch y-item row, step-0 ae row, step-0 item row ----
    float4 Y0 = make_float4(0.f, 0.f, 0.f, 0.f);
    float4 Y1 = make_float4(0.f, 0.f, 0.f, 0.f);
    if (yi != 0) {
        const float* yp = item_emb + (size_t)yi * 64;
        Y0 = *(const float4*)(yp + 4 * k8);
        Y1 = *(const float4*)(yp + 32 + 4 * k8);
    }
    // ae-row double buffer (depth-2 prefetch), slot s&1
    float4 Fb0[2], Fb1[2];
    {
        const float* ax0 = ae_raw + (size_t)xs[0] * 64;
        Fb0[0] = *(const float4*)(ax0 + 4 * k8);
        Fb1[0] = *(const float4*)(ax0 + 32 + 4 * k8);
    }
    // item-row single buffer (depth-1 prefetch)
    float4 Xc0 = make_float4(0.f, 0.f, 0.f, 0.f);
    float4 Xc1 = make_float4(0.f, 0.f, 0.f, 0.f);
    if (xs[0] != 0) {
        const float* xp = item_emb + (size_t)xs[0] * 64;
        Xc0 = *(const float4*)(xp + 4 * k8);
        Xc1 = *(const float4*)(xp + 32 + 4 * k8);
    }

    __syncthreads();   // W copy complete

    // ================= batched mat-vec: 4 b per warp ==========================
    {
        float acc0x = 0.f, acc0y = 0.f, acc1x = 0.f, acc1y = 0.f;
        float acc2x = 0.f, acc2y = 0.f, acc3x = 0.f, acc3y = 0.f;
        const int bB = warp * 4;
        const float* aey0 = sAV + (bB + 0) * 68;
        const float* aey1 = sAV + (bB + 1) * 68;
        const float* aey2 = sAV + (bB + 2) * 68;
        const float* aey3 = sAV + (bB + 3) * 68;
#pragma unroll
        for (int d4 = 0; d4 < 16; d4++) {
            float2 w0 = *(const float2*)(sW + (4 * d4 + 0) * 66 + 2 * lane);
            float2 w1 = *(const float2*)(sW + (4 * d4 + 1) * 66 + 2 * lane);
            float2 w2 = *(const float2*)(sW + (4 * d4 + 2) * 66 + 2 * lane);
            float2 w3 = *(const float2*)(sW + (4 * d4 + 3) * 66 + 2 * lane);

            float4 a;
            a = *(const float4*)(aey0 + 4 * d4);
            acc0x = fmaf(w0.x, a.x, fmaf(w1.x, a.y, fmaf(w2.x, a.z, fmaf(w3.x, a.w, acc0x))));
            acc0y = fmaf(w0.y, a.x, fmaf(w1.y, a.y, fmaf(w2.y, a.z, fmaf(w3.y, a.w, acc0y))));
            a = *(const float4*)(aey1 + 4 * d4);
            acc1x = fmaf(w0.x, a.x, fmaf(w1.x, a.y, fmaf(w2.x, a.z, fmaf(w3.x, a.w, acc1x))));
            acc1y = fmaf(w0.y, a.x, fmaf(w1.y, a.y, fmaf(w2.y, a.z, fmaf(w3.y, a.w, acc1y))));
            a = *(const float4*)(aey2 + 4 * d4);
            acc2x = fmaf(w0.x, a.x, fmaf(w1.x, a.y, fmaf(w2.x, a.z, fmaf(w3.x, a.w, acc2x))));
            acc2y = fmaf(w0.y, a.x, fmaf(w1.y, a.y, fmaf(w2.y, a.z, fmaf(w3.y, a.w, acc2y))));
            a = *(const float4*)(aey3 + 4 * d4);
            acc3x = fmaf(w0.x, a.x, fmaf(w1.x, a.y, fmaf(w2.x, a.z, fmaf(w3.x, a.w, acc3x))));
            acc3y = fmaf(w0.y, a.x, fmaf(w1.y, a.y, fmaf(w2.y, a.z, fmaf(w3.y, a.w, acc3y))));
        }
        __syncwarp();   // all aey reads done before in-place v stores
        *(float2*)(sAV + (bB + 0) * 68 + 2 * lane) = make_float2(acc0x, acc0y);
        *(float2*)(sAV + (bB + 1) * 68 + 2 * lane) = make_float2(acc1x, acc1y);
        *(float2*)(sAV + (bB + 2) * 68 + 2 * lane) = make_float2(acc2x, acc2y);
        *(float2*)(sAV + (bB + 3) * 68 + 2 * lane) = make_float2(acc3x, acc3y);
    }
    __syncwarp();

    // ================= epilogue ==============================================
    float4 V0 = *(const float4*)(sAV + bloc * 68 + 4 * k8);
    float4 V1 = *(const float4*)(sAV + bloc * 68 + 32 + 4 * k8);

    // prime depth-2: step-1 ae row
    {
        const float* ax1 = ae_raw + (size_t)xs[1] * 64;
        Fb0[1] = *(const float4*)(ax1 + 4 * k8);
        Fb1[1] = *(const float4*)(ax1 + 32 + 4 * k8);
    }

    float4 U0, U1;                       // loaded inside the final step
    float mrun = -1e30f, Zrun = 0.0f;
    float4 P0 = make_float4(0.f, 0.f, 0.f, 0.f);
    float4 P1 = make_float4(0.f, 0.f, 0.f, 0.f);

#pragma unroll
    for (int s = 0; s < SEQV; s++) {
        // this step's rows
        float4 F0 = Fb0[s & 1], F1 = Fb1[s & 1];
        float4 X0 = Xc0, X1 = Xc1;

        // refill ae slot with step s+2's row (depth-2)
        if (s + 2 < SEQV) {
            const float* axn = ae_raw + (size_t)xs[s + 2] * 64;
            Fb0[s & 1] = *(const float4*)(axn + 4 * k8);
            Fb1[s & 1] = *(const float4*)(axn + 32 + 4 * k8);
        }
        // prefetch step s+1's item row (depth-1)
        if (s + 1 < SEQV) {
            const int xn = xs[s + 1];
            if (xn != 0) {
                const float* xpn = item_emb + (size_t)xn * 64;
                Xc0 = *(const float4*)(xpn + 4 * k8);
                Xc1 = *(const float4*)(xpn + 32 + 4 * k8);
            } else {
                Xc0 = make_float4(0.f, 0.f, 0.f, 0.f);
                Xc1 = make_float4(0.f, 0.f, 0.f, 0.f);
            }
        }
        // user row: issue at the start of the last step (hidden under compute)
        if (s == SEQV - 1) {
            const float* up = user_emb + (size_t)ui * 64;
            U0 = *(const float4*)(up + 4 * k8);
            U1 = *(const float4*)(up + 32 + 4 * k8);
        }

        float f0 = F0.x * 50.0f, f1 = F0.y * 50.0f, f2 = F0.z * 50.0f, f3 = F0.w * 50.0f;
        float f4 = F1.x * 50.0f, f5 = F1.y * 50.0f, f6 = F1.z * 50.0f, f7 = F1.w * 50.0f;
        float mm = fmaxf(fmaxf(fmaxf(f0, f1), fmaxf(f2, f3)),
                         fmaxf(fmaxf(f4, f5), fmaxf(f6, f7)));
        mm = omax8(mm);
        f0 = __expf(f0 - mm); f1 = __expf(f1 - mm);
        f2 = __expf(f2 - mm); f3 = __expf(f3 - mm);
        f4 = __expf(f4 - mm); f5 = __expf(f5 - mm);
        f6 = __expf(f6 - mm); f7 = __expf(f7 - mm);
        float num = fmaf(f0, V0.x, fmaf(f1, V0.y, fmaf(f2, V0.z, f3 * V0.w)));
        num = fmaf(f4, V1.x, fmaf(f5, V1.y, fmaf(f6, V1.z, fmaf(f7, V1.w, num))));
        float den = ((f0 + f1) + (f2 + f3)) + ((f4 + f5) + (f6 + f7));
        float dot = fmaf(X0.x, Y0.x, fmaf(X0.y, Y0.y, fmaf(X0.z, Y0.z, X0.w * Y0.w)));
        dot = fmaf(X1.x, Y1.x, fmaf(X1.y, Y1.y, fmaf(X1.z, Y1.z, fmaf(X1.w, Y1.w, dot))));
        num = osum8(num);
        den = osum8(den);
        dot = osum8(dot);
        float fac = __fdividef(num, den);

        const float tf = 0.6f + 0.1f * (float)s;     // time factor, BETA=1
        float sc = dot * __expf(fac) * tf;

        // online softmax accumulation
        float mnew = fmaxf(mrun, sc);
        float r = __expf(mrun - mnew);
        float e = __expf(sc - mnew);
        Zrun = fmaf(Zrun, r, e);
        P0.x = fmaf(P0.x, r, e * X0.x); P0.y = fmaf(P0.y, r, e * X0.y);
        P0.z = fmaf(P0.z, r, e * X0.z); P0.w = fmaf(P0.w, r, e * X0.w);
        P1.x = fmaf(P1.x, r, e * X1.x); P1.y = fmaf(P1.y, r, e * X1.y);
        P1.z = fmaf(P1.z, r, e * X1.z); P1.w = fmaf(P1.w, r, e * X1.w);
        mrun = mnew;
    }

    const float scale = __fdividef(ALPHA, Zrun);
    float d;
    d =          fmaf(P0.x, scale, U0.x) * Y0.x;
    d = fmaf(fmaf(P0.y, scale, U0.y), Y0.y, d);
    d = fmaf(fmaf(P0.z, scale, U0.z), Y0.z, d);
    d = fmaf(fmaf(P0.w, scale, U0.w), Y0.w, d);
    d = fmaf(fmaf(P1.x, scale, U1.x), Y1.x, d);
    d = fmaf(fmaf(P1.y, scale, U1.y), Y1.y, d);
    d = fmaf(fmaf(P1.z, scale, U1.z), Y1.z, d);
    d = fmaf(fmaf(P1.w, scale, U1.w), Y1.w, d);
    d = osum8(d);

    if (valid && k8 == 0)
        out[b] = __fdividef(1.0f, 1.0f + __expf(-d));
}

// ---------------------------------------------------------------------------
// Launcher — inputs (metadata order): u[int B], X[int B*5], y[int B],
//   item_emb[f32 (I+1)*64], user_emb[f32 U*64], ae_raw[f32 (I+1)*64],
//   w_raw[f32 64*64].  Output: f32 [B].
// ---------------------------------------------------------------------------
extern "C" void kernel_launch(void* const* d_in, const int* in_sizes, int n_in,
                              void* d_out, int out_size) {
    const int*   u        = (const int*)  d_in[0];
    const int*   X        = (const int*)  d_in[1];
    const int*   y        = (const int*)  d_in[2];
    const float* item_emb = (const float*)d_in[3];
    const float* user_emb = (const float*)d_in[4];
    const float* ae_raw   = (const float*)d_in[5];
    const float* w_raw    = (const float*)d_in[6];
    float* out = (float*)d_out;

    const int B = in_sizes[0];

    prep_w_kernel<<<64, 64>>>(w_raw);

    const int blocks = (B + 31) / 32;   // 32 batch elems per 256-thread block
    rumc_kernel<<<blocks, 256>>>(u, X, y, item_emb, user_emb, ae_raw, out, B);
}